// round 12
// baseline (speedup 1.0000x reference)
#include <cuda_runtime.h>
#include <cuda.h>
#include <cuda_bf16.h>
#include <math.h>
#include <stdint.h>
#include <string.h>

#define NB   8
#define NH   8
#define DH   64
#define CC   512
#define NN   4096
#define HID  512
#define O3   1536
#define QSCALE 0.125f   // 64^-0.5
#define KTOT 512
#define BK   32                  // bf16 K per stage (64B rows, SW64)
#define KSTEPS (KTOT / BK)       // 16
#define TILEB (128 * 64)         // 8192 B per operand tile
#define STAGEB (4 * TILEB)       // 32768 B per stage (Ah,Al,Bh,Bl)
#define NSTAGE 6
#define PREF   5                 // prefetch distance
#define NCHUNK 8                 // ctx split-K chunks over n

// ---------------- scratch (static device arrays; sanctioned) ----------------
__device__ float g_qkv[(size_t)NB * O3 * NN];          // fp32 q|k|v (q third unused)
__device__ float g_ctx[NB * NH * DH * DH];
__device__ float g_ctxp[NCHUNK][NB * NH][DH * DH];
__device__ int   g_maskwide;
__device__ __align__(256) __nv_bfloat16 g_whi[O3 * CC],  g_wlo[O3 * CC];
__device__ __align__(256) __nv_bfloat16 g_xhi[(size_t)NB * NN * CC], g_xlo[(size_t)NB * NN * CC];
__device__ __align__(256) __nv_bfloat16 g_qhi[(size_t)NB * NN * HID], g_qlo[(size_t)NB * NN * HID];
__device__ __align__(256) __nv_bfloat16 g_wfhi[NB * CC * HID], g_wflo[NB * CC * HID];

// ---------------- device helpers ----------------
__device__ __forceinline__ uint32_t smem_u32(const void* p) {
    uint32_t a;
    asm("{ .reg .u64 t; cvta.to.shared.u64 t, %1; cvt.u32.u64 %0, t; }" : "=r"(a) : "l"(p));
    return a;
}
__device__ __forceinline__ void ldsm4(uint32_t* r, uint32_t addr) {
    asm volatile("ldmatrix.sync.aligned.m8n8.x4.shared.b16 {%0,%1,%2,%3}, [%4];"
                 : "=r"(r[0]), "=r"(r[1]), "=r"(r[2]), "=r"(r[3]) : "r"(addr));
}
__device__ __forceinline__ void mma_bf16(float* d, const uint32_t* a, uint32_t b0, uint32_t b1) {
    asm volatile("mma.sync.aligned.m16n8k16.row.col.f32.bf16.bf16.f32 "
                 "{%0,%1,%2,%3}, {%4,%5,%6,%7}, {%8,%9}, {%0,%1,%2,%3};"
                 : "+f"(d[0]), "+f"(d[1]), "+f"(d[2]), "+f"(d[3])
                 : "r"(a[0]), "r"(a[1]), "r"(a[2]), "r"(a[3]), "r"(b0), "r"(b1));
}
__device__ __forceinline__ void mbar_init(uint32_t a, uint32_t c) {
    asm volatile("mbarrier.init.shared.b64 [%0], %1;" :: "r"(a), "r"(c) : "memory");
}
__device__ __forceinline__ void mbar_expect(uint32_t a, uint32_t bytes) {
    asm volatile("mbarrier.arrive.expect_tx.shared.b64 _, [%0], %1;" :: "r"(a), "r"(bytes) : "memory");
}
__device__ __forceinline__ void mbar_wait(uint32_t mbar, uint32_t parity) {
    uint32_t done;
    asm volatile("{ .reg .pred p; mbarrier.try_wait.parity.acquire.cta.shared::cta.b64 p, [%1], %2; selp.b32 %0,1,0,p; }"
                 : "=r"(done) : "r"(mbar), "r"(parity) : "memory");
    if (!done) {
        asm volatile("{ .reg .pred P1; WL%=: mbarrier.try_wait.parity.acquire.cta.shared::cta.b64 P1, [%0], %1, 0x989680; @P1 bra.uni WD%=; bra.uni WL%=; WD%=: }"
                     :: "r"(mbar), "r"(parity) : "memory");
    }
}
__device__ __forceinline__ void tma3d(uint32_t dst, const CUtensorMap* m,
                                      int cx, int cy, int cz, uint32_t bar) {
    asm volatile("cp.async.bulk.tensor.3d.shared::cta.global.tile.mbarrier::complete_tx::bytes "
                 "[%0], [%1, {%2, %3, %4}], [%5];"
                 :: "r"(dst), "l"(m), "r"(cx), "r"(cy), "r"(cz), "r"(bar) : "memory");
}
__device__ __forceinline__ void split_bf16(float v, __nv_bfloat16& hi, __nv_bfloat16& lo) {
    hi = __float2bfloat16(v);
    lo = __float2bfloat16(v - __bfloat162float(hi));
}
__device__ __forceinline__ unsigned short bfbits(__nv_bfloat16 x) {
    unsigned short u; memcpy(&u, &x, 2); return u;
}

// ---------------------------------------------------------------------------
__global__ void sniff_mask_kernel(const unsigned char* __restrict__ mask8) {
    g_maskwide = (mask8[1] == 0) ? 1 : 0;
}

__global__ __launch_bounds__(256) void convert_w_kernel(const float* __restrict__ w) {
    int i = blockIdx.x * 256 + threadIdx.x;
    if (i < O3 * CC) { __nv_bfloat16 h, l; split_bf16(w[i], h, l); g_whi[i] = h; g_wlo[i] = l; }
}

// x [b][c][n] fp32 -> xT hi/lo [b][n][c] bf16.
__global__ __launch_bounds__(256) void transpose_convert_x(const float* __restrict__ x) {
    __shared__ float t[64][33];
    const int b = blockIdx.z, n0 = blockIdx.x * 32, c0 = blockIdx.y * 64;
    const int tx = threadIdx.x, ty = threadIdx.y;              // 32 x 8
    #pragma unroll
    for (int cl = ty; cl < 64; cl += 8)
        t[cl][tx] = x[((long)b * CC + c0 + cl) * NN + n0 + tx];
    __syncthreads();
    const int lane = tx;
    #pragma unroll
    for (int rr = 0; rr < 4; rr++) {
        const int r = ty * 4 + rr;
        float v0 = t[2 * lane][r], v1 = t[2 * lane + 1][r];
        __nv_bfloat16 h0, l0, h1, l1;
        split_bf16(v0, h0, l0); split_bf16(v1, h1, l1);
        const long base = ((long)b * NN + n0 + r) * CC + c0 + 2 * lane;
        *(uint32_t*)&g_xhi[base] = (uint32_t)bfbits(h0) | ((uint32_t)bfbits(h1) << 16);
        *(uint32_t*)&g_xlo[base] = (uint32_t)bfbits(l0) | ((uint32_t)bfbits(l1) << 16);
    }
}

// ---------------------------------------------------------------------------
// bf16x3 GEMM: TMA (SW64, 64B rows) + mma.sync. 128x128 CTA tile, 256 thr,
// warps 2x4, warp tile 64x32, BK=32, 6-stage pipeline with prefetch distance 5
// (issue BEFORE compute each step). QFUSE: q m-tiles get fused column-softmax
// + bf16 hi/lo split, written coalesced via smem staging.
// ---------------------------------------------------------------------------
template<bool BIAS, bool QFUSE>
__global__ __launch_bounds__(256, 1)
void tma_gemm_kernel(const __grid_constant__ CUtensorMap tAh,
                     const __grid_constant__ CUtensorMap tAl,
                     const __grid_constant__ CUtensorMap tBh,
                     const __grid_constant__ CUtensorMap tBl,
                     float* __restrict__ C, const float* __restrict__ bias,
                     long sC, int ldC, int aBatch)
{
    extern __shared__ char dsmem[];
    __shared__ __align__(8) unsigned long long s_bar[NSTAGE];

    const int tid = threadIdx.x, lane = tid & 31, wid = tid >> 5;
    const int wm = wid >> 2, wn = wid & 3;            // warps 2x4
    const int m0 = blockIdx.y * 128, n0 = blockIdx.x * 128, bz = blockIdx.z;
    const int za = aBatch ? bz : 0;

    const uint32_t sb = (smem_u32(dsmem) + 1023u) & ~1023u;
    const uint32_t bar0 = smem_u32(&s_bar[0]);

    if (tid == 0) {
        #pragma unroll
        for (int i = 0; i < NSTAGE; i++) mbar_init(bar0 + i * 8, 1);
    }
    asm volatile("fence.proxy.async.shared::cta;" ::: "memory");
    __syncthreads();

    auto issue = [&](int s) {
        const int sl = s % NSTAGE;
        const uint32_t bar = bar0 + sl * 8;
        const uint32_t dst = sb + sl * STAGEB;
        const int k0 = s * BK;
        mbar_expect(bar, STAGEB);
        tma3d(dst,             &tAh, k0, m0, za, bar);
        tma3d(dst + TILEB,     &tAl, k0, m0, za, bar);
        tma3d(dst + 2 * TILEB, &tBh, k0, n0, bz, bar);
        tma3d(dst + 3 * TILEB, &tBl, k0, n0, bz, bar);
    };
    if (tid == 0) {
        #pragma unroll
        for (int i = 0; i < PREF; i++) issue(i);
    }

    // ldmatrix SW64 addressing: 64B rows, xor nibble = (row>>1)&3 (row = lane&15
    // only — warp/mf offsets are multiples of 8 rows and contribute 0).
    const int lr = lane & 15;
    const int cb = lane >> 4;                     // 16B chunk within k16 (0/1)
    const uint32_t x4 = (uint32_t)((lr >> 1) & 3);
    const uint32_t aRow = (uint32_t)((wm * 64 + lr) * 64);
    const uint32_t bRow = (uint32_t)((wn * 32 + lr) * 64);

    float acc[4][4][4];
    #pragma unroll
    for (int i = 0; i < 4; i++)
        #pragma unroll
        for (int j = 0; j < 4; j++)
            #pragma unroll
            for (int r = 0; r < 4; r++) acc[i][j][r] = 0.f;

    for (int s = 0; s < KSTEPS; s++) {
        mbar_wait(bar0 + (s % NSTAGE) * 8, (uint32_t)((s / NSTAGE) & 1));
        __syncthreads();   // all warps done with compute(s-1): buffer (s+PREF)%6 free
        if (tid == 0 && s + PREF < KSTEPS) issue(s + PREF);

        const uint32_t stg = sb + (s % NSTAGE) * STAGEB;
        #pragma unroll
        for (int k16 = 0; k16 < 2; k16++) {
            const uint32_t csw = (uint32_t)(((uint32_t)(k16 * 2 + cb) ^ x4) * 16);
            uint32_t ah[4][4], al[4][4], bhf[2][4], blf[2][4];
            #pragma unroll
            for (int mf = 0; mf < 4; mf++) {
                const uint32_t ro = aRow + (uint32_t)(mf * 16 * 64) + csw;
                ldsm4(ah[mf], stg + ro);
                ldsm4(al[mf], stg + TILEB + ro);
            }
            #pragma unroll
            for (int nf = 0; nf < 2; nf++) {
                const uint32_t ro = bRow + (uint32_t)(nf * 16 * 64) + csw;
                ldsm4(bhf[nf], stg + 2 * TILEB + ro);
                ldsm4(blf[nf], stg + 3 * TILEB + ro);
            }
            #pragma unroll
            for (int t = 0; t < 3; t++) {
                #pragma unroll
                for (int mf = 0; mf < 4; mf++) {
                    #pragma unroll
                    for (int j = 0; j < 4; j++) {
                        const int nf = j >> 1, sel = j & 1;
                        if (t == 0)
                            mma_bf16(acc[mf][j], ah[mf], bhf[nf][sel], bhf[nf][sel + 2]);
                        else if (t == 1)
                            mma_bf16(acc[mf][j], ah[mf], blf[nf][sel], blf[nf][sel + 2]);
                        else
                            mma_bf16(acc[mf][j], al[mf], bhf[nf][sel], bhf[nf][sel + 2]);
                    }
                }
            }
        }
    }

    // epilogue: fragments -> smem eps[128][132] fp32
    __syncthreads();
    float* eps = (float*)dsmem;
    const int fr = lane >> 2, fc = (lane & 3) * 2;
    #pragma unroll
    for (int mf = 0; mf < 4; mf++) {
        #pragma unroll
        for (int j = 0; j < 4; j++) {
            const int row = wm * 64 + mf * 16 + fr;
            const int col = wn * 32 + j * 8 + fc;
            eps[row * 132 + col]           = acc[mf][j][0];
            eps[row * 132 + col + 1]       = acc[mf][j][1];
            eps[(row + 8) * 132 + col]     = acc[mf][j][2];
            eps[(row + 8) * 132 + col + 1] = acc[mf][j][3];
        }
    }
    __syncthreads();

    if (QFUSE && m0 < 512) {
        // fused q softmax: thread -> (column n = tid&127, head group g = tid>>7, 2 groups)
        const int col = tid & 127, g = tid >> 7;
        float* ep = eps + (g * 64) * 132 + col;
        float mx = -INFINITY;
        #pragma unroll
        for (int d = 0; d < 64; d++) mx = fmaxf(mx, ep[d * 132]);
        float sum = 0.f;
        #pragma unroll
        for (int d = 0; d < 64; d++) { float e = __expf(ep[d * 132] - mx); sum += e; ep[d * 132] = e; }
        const float inv = QSCALE / sum;

        // staging after eps: qb[g][col][33] u32 (conflict-free both directions)
        uint32_t* qb = (uint32_t*)(dsmem + 128 * 132 * 4);
        #pragma unroll
        for (int part = 0; part < 2; part++) {          // 0 = hi, 1 = lo
            uint32_t* qrow = qb + (g * 128 + col) * 33;
            #pragma unroll
            for (int p = 0; p < 32; p++) {
                float v0 = ep[(2 * p) * 132] * inv;
                float v1 = ep[(2 * p + 1) * 132] * inv;
                __nv_bfloat16 h0, l0, h1, l1;
                split_bf16(v0, h0, l0); split_bf16(v1, h1, l1);
                qrow[p] = (part == 0)
                    ? ((uint32_t)bfbits(h0) | ((uint32_t)bfbits(h1) << 16))
                    : ((uint32_t)bfbits(l0) | ((uint32_t)bfbits(l1) << 16));
            }
            __syncthreads();
            {   // coalesced writers: 8 warps = 2 groups x 4 col-chunks
                const int wg = wid >> 2, ch = wid & 3;
                uint32_t* dst = (part == 0) ? (uint32_t*)g_qhi : (uint32_t*)g_qlo;
                #pragma unroll
                for (int c = 0; c < 32; c++) {
                    const int colx = ch * 32 + c;
                    const long u = ((long)bz * NN + n0 + colx) * (HID / 2)
                                 + (m0 + wg * 64) / 2 + lane;
                    dst[u] = qb[(wg * 128 + colx) * 33 + lane];
                }
            }
            __syncthreads();
        }
    } else {
        float* Cp = C + (long)bz * sC + (long)m0 * ldC + n0;
        for (int i = tid; i < 128 * 32; i += 256) {
            const int r = i >> 5, c4 = (i & 31) << 2;
            float4 v = *(float4*)&eps[r * 132 + c4];
            if (BIAS) {
                const float bv = bias[m0 + r];
                v.x += bv; v.y += bv; v.z += bv; v.w += bv;
            }
            *(float4*)&Cp[(long)r * ldC + c4] = v;
        }
    }
}

// ---------------------------------------------------------------------------
// k: mask + softmax over n (4096). In-place fp32.
__global__ __launch_bounds__(256)
void softmax_k_kernel(const unsigned char* __restrict__ mask8)
{
    const int row = blockIdx.x;
    const int b = row >> 9;
    float* p = g_qkv + ((long)b * O3 + HID + (row & 511)) * NN;

    __shared__ float sv[NN];
    __shared__ float red[256];
    const int tid = threadIdx.x;
    const bool wide = (g_maskwide != 0);
    const int* mask32 = (const int*)mask8;

    float m = -INFINITY;
    for (int i = tid; i < NN; i += 256) {
        const bool on = wide ? (mask32[b * NN + i] != 0) : (mask8[b * NN + i] != 0);
        const float x = on ? p[i] : -INFINITY;
        sv[i] = x;
        m = fmaxf(m, x);
    }
    red[tid] = m; __syncthreads();
    for (int s = 128; s > 0; s >>= 1) { if (tid < s) red[tid] = fmaxf(red[tid], red[tid + s]); __syncthreads(); }
    m = red[0]; __syncthreads();

    float sum = 0.f;
    for (int i = tid; i < NN; i += 256) { const float e = __expf(sv[i] - m); sv[i] = e; sum += e; }
    red[tid] = sum; __syncthreads();
    for (int s = 128; s > 0; s >>= 1) { if (tid < s) red[tid] += red[tid + s]; __syncthreads(); }
    const float inv = 1.f / red[0];
    for (int i = tid; i < NN; i += 256) p[i] = sv[i] * inv;
}

// ---------------------------------------------------------------------------
__global__ __launch_bounds__(256)
void ctx_part_kernel()
{
    const int bh = blockIdx.x, ck = blockIdx.y;
    const int b = bh >> 3, h = bh & 7;
    const float* Kp = g_qkv + ((long)b * O3 + HID     + h * DH) * NN;
    const float* Vp = g_qkv + ((long)b * O3 + 2 * HID + h * DH) * NN;
    const int nbeg = ck * (NN / NCHUNK), nend = nbeg + (NN / NCHUNK);

    __shared__ float Ks[32][64];
    __shared__ float Vs[32][64];
    const int tid = threadIdx.x;
    const int lr = tid >> 2, lc = (tid & 3) << 3;
    const int tx = tid & 15, ty = tid >> 4;

    float acc[4][4];
    #pragma unroll
    for (int i = 0; i < 4; i++)
        #pragma unroll
        for (int j = 0; j < 4; j++) acc[i][j] = 0.f;

    for (int n0 = nbeg; n0 < nend; n0 += 32) {
        float4 ka = *(const float4*)(Kp + (long)lr * NN + n0 + lc);
        float4 kb = *(const float4*)(Kp + (long)lr * NN + n0 + lc + 4);
        float4 va = *(const float4*)(Vp + (long)lr * NN + n0 + lc);
        float4 vb = *(const float4*)(Vp + (long)lr * NN + n0 + lc + 4);
        Ks[lc + 0][lr] = ka.x; Ks[lc + 1][lr] = ka.y; Ks[lc + 2][lr] = ka.z; Ks[lc + 3][lr] = ka.w;
        Ks[lc + 4][lr] = kb.x; Ks[lc + 5][lr] = kb.y; Ks[lc + 6][lr] = kb.z; Ks[lc + 7][lr] = kb.w;
        Vs[lc + 0][lr] = va.x; Vs[lc + 1][lr] = va.y; Vs[lc + 2][lr] = va.z; Vs[lc + 3][lr] = va.w;
        Vs[lc + 4][lr] = vb.x; Vs[lc + 5][lr] = vb.y; Vs[lc + 6][lr] = vb.z; Vs[lc + 7][lr] = vb.w;
        __syncthreads();
        #pragma unroll
        for (int c = 0; c < 32; c++) {
            float4 k4 = *(const float4*)&Ks[c][ty * 4];
            float4 v4 = *(const float4*)&Vs[c][tx * 4];
            const float kr[4] = { k4.x, k4.y, k4.z, k4.w };
            const float vr[4] = { v4.x, v4.y, v4.z, v4.w };
            #pragma unroll
            for (int i = 0; i < 4; i++)
                #pragma unroll
                for (int j = 0; j < 4; j++)
                    acc[i][j] = fmaf(kr[i], vr[j], acc[i][j]);
        }
        __syncthreads();
    }
    float* Cp = g_ctxp[ck][bh];
    #pragma unroll
    for (int i = 0; i < 4; i++)
        #pragma unroll
        for (int j = 0; j < 4; j++)
            Cp[(ty * 4 + i) * DH + tx * 4 + j] = acc[i][j];
}

__global__ __launch_bounds__(256)
void ctx_reduce_kernel()
{
    const int idx = blockIdx.x * 256 + threadIdx.x;
    const int bh = idx >> 12, e = idx & 4095;
    float s = 0.f;
    #pragma unroll
    for (int c = 0; c < NCHUNK; c++) s += g_ctxp[c][bh][e];
    g_ctx[(long)bh * (DH * DH) + e] = s;
}

// ---------------------------------------------------------------------------
// Weff tiled mini-GEMM -> bf16 hi/lo.
__global__ __launch_bounds__(256)
void weff_kernel(const float* __restrict__ w_out)
{
    const int bh = blockIdx.x, oc = blockIdx.y;
    const int b = bh >> 3, h = bh & 7;
    const int o0 = oc * 64;

    __shared__ float ws[64][68];
    __shared__ float cs[64][68];
    const int tid = threadIdx.x;

    for (int i = tid; i < 64 * 64; i += 256) {
        const int r = i >> 6, e = i & 63;
        ws[e][r] = w_out[(long)(o0 + r) * HID + h * DH + e];
        cs[e][r] = g_ctx[((long)bh * DH + r) * DH + e];
    }
    __syncthreads();

    const int txx = tid & 15, tyy = tid >> 4;
    float acc[4][4];
    #pragma unroll
    for (int i = 0; i < 4; i++)
        #pragma unroll
        for (int j = 0; j < 4; j++) acc[i][j] = 0.f;

    #pragma unroll 4
    for (int e = 0; e < 64; e++) {
        float4 w4 = *(const float4*)&ws[e][tyy * 4];
        float4 c4 = *(const float4*)&cs[e][txx * 4];
        const float wr[4] = { w4.x, w4.y, w4.z, w4.w };
        const float cr[4] = { c4.x, c4.y, c4.z, c4.w };
        #pragma unroll
        for (int i = 0; i < 4; i++)
            #pragma unroll
            for (int j = 0; j < 4; j++)
                acc[i][j] = fmaf(wr[i], cr[j], acc[i][j]);
    }

    #pragma unroll
    for (int i = 0; i < 4; i++) {
        const long base = ((long)b * CC + o0 + tyy * 4 + i) * HID + h * DH + txx * 4;
        __nv_bfloat16 h0, l0, h1, l1, h2, l2, h3, l3;
        split_bf16(acc[i][0], h0, l0); split_bf16(acc[i][1], h1, l1);
        split_bf16(acc[i][2], h2, l2); split_bf16(acc[i][3], h3, l3);
        *(uint2*)&g_wfhi[base] = make_uint2(
            (uint32_t)bfbits(h0) | ((uint32_t)bfbits(h1) << 16),
            (uint32_t)bfbits(h2) | ((uint32_t)bfbits(h3) << 16));
        *(uint2*)&g_wflo[base] = make_uint2(
            (uint32_t)bfbits(l0) | ((uint32_t)bfbits(l1) << 16),
            (uint32_t)bfbits(l2) | ((uint32_t)bfbits(l3) << 16));
    }
}

// ---------------------------------------------------------------------------
typedef CUresult (*EncFn)(CUtensorMap*, CUtensorMapDataType, cuuint32_t, void*,
                          const cuuint64_t*, const cuuint64_t*, const cuuint32_t*,
                          const cuuint32_t*, CUtensorMapInterleave, CUtensorMapSwizzle,
                          CUtensorMapL2promotion, CUtensorMapFloatOOBfill);

static void make_desc(EncFn enc, CUtensorMap* m, void* base,
                      uint64_t d0, uint64_t d1, uint64_t d2)
{
    cuuint64_t dims[3] = { d0, d1, d2 };
    cuuint64_t strides[2] = { d0 * 2, d0 * d1 * 2 };
    cuuint32_t box[3] = { 32, 128, 1 };          // 64B rows -> SW64
    cuuint32_t es[3] = { 1, 1, 1 };
    enc(m, CU_TENSOR_MAP_DATA_TYPE_BFLOAT16, 3, base, dims, strides, box, es,
        CU_TENSOR_MAP_INTERLEAVE_NONE, CU_TENSOR_MAP_SWIZZLE_64B,
        CU_TENSOR_MAP_L2_PROMOTION_L2_128B, CU_TENSOR_MAP_FLOAT_OOB_FILL_NONE);
}

extern "C" void kernel_launch(void* const* d_in, const int* in_sizes, int n_in,
                              void* d_out, int out_size)
{
    const float* x      = (const float*)d_in[0];
    const unsigned char* mask = (const unsigned char*)d_in[1];
    const float* w_qkv  = (const float*)d_in[2];
    const float* w_out  = (const float*)d_in[3];
    const float* b_out  = (const float*)d_in[4];
    float* out = (float*)d_out;

    float *qkv_p;
    __nv_bfloat16 *whi_p, *wlo_p, *xhi_p, *xlo_p, *qhi_p, *qlo_p, *wfhi_p, *wflo_p;
    cudaGetSymbolAddress((void**)&qkv_p,  g_qkv);
    cudaGetSymbolAddress((void**)&whi_p,  g_whi);
    cudaGetSymbolAddress((void**)&wlo_p,  g_wlo);
    cudaGetSymbolAddress((void**)&xhi_p,  g_xhi);
    cudaGetSymbolAddress((void**)&xlo_p,  g_xlo);
    cudaGetSymbolAddress((void**)&qhi_p,  g_qhi);
    cudaGetSymbolAddress((void**)&qlo_p,  g_qlo);
    cudaGetSymbolAddress((void**)&wfhi_p, g_wfhi);
    cudaGetSymbolAddress((void**)&wflo_p, g_wflo);

    void* encf = nullptr;
    cudaDriverEntryPointQueryResult qr;
    cudaGetDriverEntryPoint("cuTensorMapEncodeTiled", &encf, cudaEnableDefault, &qr);
    EncFn enc = (EncFn)encf;

    CUtensorMap tWh, tWl, tXh, tXl, tQh, tQl, tFh, tFl;
    make_desc(enc, &tWh, whi_p,  512, 1536, 1);
    make_desc(enc, &tWl, wlo_p,  512, 1536, 1);
    make_desc(enc, &tXh, xhi_p,  512, 4096, 8);
    make_desc(enc, &tXl, xlo_p,  512, 4096, 8);
    make_desc(enc, &tQh, qhi_p,  512, 4096, 8);
    make_desc(enc, &tQl, qlo_p,  512, 4096, 8);
    make_desc(enc, &tFh, wfhi_p, 512, 512,  8);
    make_desc(enc, &tFl, wflo_p, 512, 512,  8);

    const int DSMEM = NSTAGE * STAGEB + 1024;   // 197632 B
    cudaFuncSetAttribute((const void*)tma_gemm_kernel<false, true>,
                         cudaFuncAttributeMaxDynamicSharedMemorySize, DSMEM);
    cudaFuncSetAttribute((const void*)tma_gemm_kernel<true, false>,
                         cudaFuncAttributeMaxDynamicSharedMemorySize, DSMEM);

    // 0) prep
    sniff_mask_kernel<<<1, 1>>>(mask);
    convert_w_kernel<<<(O3 * CC + 255) / 256, 256>>>(w_qkv);
    {
        dim3 g(NN / 32, CC / 64, NB);
        transpose_convert_x<<<g, dim3(32, 8)>>>(x);
    }
    // 1) qkv = w_qkv @ x  (TMA SW64 + mma.sync bf16x3; q tiles fused softmax)
    {
        dim3 g(NN / 128, O3 / 128, NB);
        tma_gemm_kernel<false, true><<<g, 256, DSMEM>>>(
            tWh, tWl, tXh, tXl, qkv_p, nullptr, (long)O3 * NN, NN, 0);
    }
    // 2) k mask + softmax (in place, fp32)
    softmax_k_kernel<<<NB * HID, 256>>>(mask);
    // 3) context: split-K partials + deterministic reduce
    {
        dim3 g(NB * NH, NCHUNK);
        ctx_part_kernel<<<g, 256>>>();
        ctx_reduce_kernel<<<(NB * NH * DH * DH) / 256, 256>>>();
    }
    // 4) Weff (folded w_out x ctx) -> bf16 hi/lo
    {
        dim3 g(NB * NH, CC / 64);
        weff_kernel<<<g, 256>>>(w_out);
    }
    // 5) out = Weff[b] @ qT[b]^T + b_out
    {
        dim3 g(NN / 128, CC / 128, NB);
        tma_gemm_kernel<true, false><<<g, 256, DSMEM>>>(
            tFh, tFl, tQh, tQl, out, b_out, (long)CC * NN, NN, 1);
    }
}

// round 14
// speedup vs baseline: 1.0381x; 1.0381x over previous
#include <cuda_runtime.h>
#include <cuda.h>
#include <cuda_bf16.h>
#include <math.h>
#include <stdint.h>
#include <string.h>

#define NB   8
#define NH   8
#define DH   64
#define CC   512
#define NN   4096
#define HID  512
#define O3   1536
#define QSCALE 0.125f   // 64^-0.5
#define KTOT 512
#define BK   64                  // bf16 K per stage (128B rows, SW128)
#define KSTEPS (KTOT / BK)       // 8
#define TILEB (128 * 128)        // 16384 B per operand tile
#define STAGEB (4 * TILEB)       // 65536 B per stage (Ah,Al,Bh,Bl)
#define NSTAGE 3
#define NCHUNK 8                 // ctx split-K chunks over n

// ---------------- scratch (static device arrays; sanctioned) ----------------
__device__ float g_qkv[(size_t)NB * O3 * NN];          // fp32 q|k|v (q third unused)
__device__ float g_ctx[NB * NH * DH * DH];
__device__ float g_ctxp[NCHUNK][NB * NH][DH * DH];
__device__ int   g_maskwide;
__device__ __align__(256) __nv_bfloat16 g_whi[O3 * CC],  g_wlo[O3 * CC];
__device__ __align__(256) __nv_bfloat16 g_xhi[(size_t)NB * NN * CC], g_xlo[(size_t)NB * NN * CC];
__device__ __align__(256) __nv_bfloat16 g_qhi[(size_t)NB * NN * HID], g_qlo[(size_t)NB * NN * HID];
__device__ __align__(256) __nv_bfloat16 g_wfhi[NB * CC * HID], g_wflo[NB * CC * HID];

// ---------------- device helpers ----------------
__device__ __forceinline__ uint32_t smem_u32(const void* p) {
    uint32_t a;
    asm("{ .reg .u64 t; cvta.to.shared.u64 t, %1; cvt.u32.u64 %0, t; }" : "=r"(a) : "l"(p));
    return a;
}
__device__ __forceinline__ void ldsm4(uint32_t* r, uint32_t addr) {
    asm volatile("ldmatrix.sync.aligned.m8n8.x4.shared.b16 {%0,%1,%2,%3}, [%4];"
                 : "=r"(r[0]), "=r"(r[1]), "=r"(r[2]), "=r"(r[3]) : "r"(addr));
}
__device__ __forceinline__ void mma_bf16(float* d, const uint32_t* a, uint32_t b0, uint32_t b1) {
    asm volatile("mma.sync.aligned.m16n8k16.row.col.f32.bf16.bf16.f32 "
                 "{%0,%1,%2,%3}, {%4,%5,%6,%7}, {%8,%9}, {%0,%1,%2,%3};"
                 : "+f"(d[0]), "+f"(d[1]), "+f"(d[2]), "+f"(d[3])
                 : "r"(a[0]), "r"(a[1]), "r"(a[2]), "r"(a[3]), "r"(b0), "r"(b1));
}
__device__ __forceinline__ void mbar_init(uint32_t a, uint32_t c) {
    asm volatile("mbarrier.init.shared.b64 [%0], %1;" :: "r"(a), "r"(c) : "memory");
}
__device__ __forceinline__ void mbar_expect(uint32_t a, uint32_t bytes) {
    asm volatile("mbarrier.arrive.expect_tx.shared.b64 _, [%0], %1;" :: "r"(a), "r"(bytes) : "memory");
}
__device__ __forceinline__ void mbar_wait(uint32_t mbar, uint32_t parity) {
    uint32_t done;
    asm volatile("{ .reg .pred p; mbarrier.try_wait.parity.acquire.cta.shared::cta.b64 p, [%1], %2; selp.b32 %0,1,0,p; }"
                 : "=r"(done) : "r"(mbar), "r"(parity) : "memory");
    if (!done) {
        asm volatile("{ .reg .pred P1; WL%=: mbarrier.try_wait.parity.acquire.cta.shared::cta.b64 P1, [%0], %1, 0x989680; @P1 bra.uni WD%=; bra.uni WL%=; WD%=: }"
                     :: "r"(mbar), "r"(parity) : "memory");
    }
}
__device__ __forceinline__ void tma3d(uint32_t dst, const CUtensorMap* m,
                                      int cx, int cy, int cz, uint32_t bar) {
    asm volatile("cp.async.bulk.tensor.3d.shared::cta.global.tile.mbarrier::complete_tx::bytes "
                 "[%0], [%1, {%2, %3, %4}], [%5];"
                 :: "r"(dst), "l"(m), "r"(cx), "r"(cy), "r"(cz), "r"(bar) : "memory");
}
__device__ __forceinline__ void split_bf16(float v, __nv_bfloat16& hi, __nv_bfloat16& lo) {
    hi = __float2bfloat16(v);
    lo = __float2bfloat16(v - __bfloat162float(hi));
}
__device__ __forceinline__ unsigned short bfbits(__nv_bfloat16 x) {
    unsigned short u; memcpy(&u, &x, 2); return u;
}

// ---------------------------------------------------------------------------
__global__ void sniff_mask_kernel(const unsigned char* __restrict__ mask8) {
    g_maskwide = (mask8[1] == 0) ? 1 : 0;
}

__global__ __launch_bounds__(256) void convert_w_kernel(const float* __restrict__ w) {
    int i = blockIdx.x * 256 + threadIdx.x;
    if (i < O3 * CC) { __nv_bfloat16 h, l; split_bf16(w[i], h, l); g_whi[i] = h; g_wlo[i] = l; }
}

// x [b][c][n] fp32 -> xT hi/lo [b][n][c] bf16.
__global__ __launch_bounds__(256) void transpose_convert_x(const float* __restrict__ x) {
    __shared__ float t[64][33];
    const int b = blockIdx.z, n0 = blockIdx.x * 32, c0 = blockIdx.y * 64;
    const int tx = threadIdx.x, ty = threadIdx.y;              // 32 x 8
    #pragma unroll
    for (int cl = ty; cl < 64; cl += 8)
        t[cl][tx] = x[((long)b * CC + c0 + cl) * NN + n0 + tx];
    __syncthreads();
    const int lane = tx;
    #pragma unroll
    for (int rr = 0; rr < 4; rr++) {
        const int r = ty * 4 + rr;
        float v0 = t[2 * lane][r], v1 = t[2 * lane + 1][r];
        __nv_bfloat16 h0, l0, h1, l1;
        split_bf16(v0, h0, l0); split_bf16(v1, h1, l1);
        const long base = ((long)b * NN + n0 + r) * CC + c0 + 2 * lane;
        *(uint32_t*)&g_xhi[base] = (uint32_t)bfbits(h0) | ((uint32_t)bfbits(h1) << 16);
        *(uint32_t*)&g_xlo[base] = (uint32_t)bfbits(l0) | ((uint32_t)bfbits(l1) << 16);
    }
}

// ---------------------------------------------------------------------------
// bf16x3 GEMM: TMA (SW128) + mma.sync. 128x128 CTA tile, 256 thr, warps 2x4,
// warp tile 64x32, BK=64, 3-stage pipeline (R9-proven loop order).
// QFUSE: q m-tiles get fused column-softmax + bf16 hi/lo split, coalesced.
// ---------------------------------------------------------------------------
template<bool BIAS, bool QFUSE>
__global__ __launch_bounds__(256, 1)
void tma_gemm_kernel(const __grid_constant__ CUtensorMap tAh,
                     const __grid_constant__ CUtensorMap tAl,
                     const __grid_constant__ CUtensorMap tBh,
                     const __grid_constant__ CUtensorMap tBl,
                     float* __restrict__ C, const float* __restrict__ bias,
                     long sC, int ldC, int aBatch)
{
    extern __shared__ char dsmem[];
    __shared__ __align__(8) unsigned long long s_bar[NSTAGE];

    const int tid = threadIdx.x, lane = tid & 31, wid = tid >> 5;
    const int wm = wid >> 2, wn = wid & 3;            // warps 2x4
    const int m0 = blockIdx.y * 128, n0 = blockIdx.x * 128, bz = blockIdx.z;
    const int za = aBatch ? bz : 0;

    const uint32_t sb = (smem_u32(dsmem) + 1023u) & ~1023u;
    const uint32_t bar0 = smem_u32(&s_bar[0]);

    if (tid == 0) {
        #pragma unroll
        for (int i = 0; i < NSTAGE; i++) mbar_init(bar0 + i * 8, 1);
    }
    asm volatile("fence.proxy.async.shared::cta;" ::: "memory");
    __syncthreads();

    auto issue = [&](int s) {
        const int sl = s % NSTAGE;
        const uint32_t bar = bar0 + sl * 8;
        const uint32_t dst = sb + sl * STAGEB;
        const int k0 = s * BK;
        mbar_expect(bar, STAGEB);
        tma3d(dst,             &tAh, k0, m0, za, bar);
        tma3d(dst + TILEB,     &tAl, k0, m0, za, bar);
        tma3d(dst + 2 * TILEB, &tBh, k0, n0, bz, bar);
        tma3d(dst + 3 * TILEB, &tBl, k0, n0, bz, bar);
    };
    if (tid == 0) { issue(0); issue(1); issue(2); }

    // ldmatrix swizzled addressing (SW128, 128B rows)
    const int lr = lane & 15;
    const uint32_t xorv = (uint32_t)((lane & 7) << 4);
    const uint32_t acol = (uint32_t)((lane >> 4) * 16);
    const uint32_t aRow = (uint32_t)((wm * 64 + lr) * 128);
    const uint32_t bRow = (uint32_t)((wn * 32 + lr) * 128);

    float acc[4][4][4];
    #pragma unroll
    for (int i = 0; i < 4; i++)
        #pragma unroll
        for (int j = 0; j < 4; j++)
            #pragma unroll
            for (int r = 0; r < 4; r++) acc[i][j][r] = 0.f;

    for (int s = 0; s < KSTEPS; s++) {
        mbar_wait(bar0 + (s % NSTAGE) * 8, (uint32_t)((s / NSTAGE) & 1));
        const uint32_t stg = sb + (s % NSTAGE) * STAGEB;

        #pragma unroll
        for (int k16 = 0; k16 < 4; k16++) {
            const uint32_t kb = (uint32_t)(k16 * 32);
            const uint32_t csw = (acol + kb) ^ xorv;
            uint32_t ah[4][4], al[4][4], bhf[2][4], blf[2][4];
            #pragma unroll
            for (int mf = 0; mf < 4; mf++) {
                const uint32_t ro = aRow + (uint32_t)(mf * 16 * 128) + csw;
                ldsm4(ah[mf], stg + ro);
                ldsm4(al[mf], stg + TILEB + ro);
            }
            #pragma unroll
            for (int nf = 0; nf < 2; nf++) {
                const uint32_t ro = bRow + (uint32_t)(nf * 16 * 128) + csw;
                ldsm4(bhf[nf], stg + 2 * TILEB + ro);
                ldsm4(blf[nf], stg + 3 * TILEB + ro);
            }
            #pragma unroll
            for (int t = 0; t < 3; t++) {
                #pragma unroll
                for (int mf = 0; mf < 4; mf++) {
                    #pragma unroll
                    for (int j = 0; j < 4; j++) {
                        const int nf = j >> 1, sel = j & 1;
                        if (t == 0)
                            mma_bf16(acc[mf][j], ah[mf], bhf[nf][sel], bhf[nf][sel + 2]);
                        else if (t == 1)
                            mma_bf16(acc[mf][j], ah[mf], blf[nf][sel], blf[nf][sel + 2]);
                        else
                            mma_bf16(acc[mf][j], al[mf], bhf[nf][sel], bhf[nf][sel + 2]);
                    }
                }
            }
        }

        __syncthreads();
        if (s + NSTAGE < KSTEPS && tid == 0) issue(s + NSTAGE);
    }

    // epilogue: fragments -> smem eps[128][132] fp32
    __syncthreads();
    float* eps = (float*)dsmem;
    const int fr = lane >> 2, fc = (lane & 3) * 2;
    #pragma unroll
    for (int mf = 0; mf < 4; mf++) {
        #pragma unroll
        for (int j = 0; j < 4; j++) {
            const int row = wm * 64 + mf * 16 + fr;
            const int col = wn * 32 + j * 8 + fc;
            eps[row * 132 + col]           = acc[mf][j][0];
            eps[row * 132 + col + 1]       = acc[mf][j][1];
            eps[(row + 8) * 132 + col]     = acc[mf][j][2];
            eps[(row + 8) * 132 + col + 1] = acc[mf][j][3];
        }
    }
    __syncthreads();

    if (QFUSE && m0 < 512) {
        // fused q softmax: thread -> (column n = tid&127, head group g = tid>>7)
        const int col = tid & 127, g = tid >> 7;
        float* ep = eps + (g * 64) * 132 + col;
        float mx = -INFINITY;
        #pragma unroll
        for (int d = 0; d < 64; d++) mx = fmaxf(mx, ep[d * 132]);
        float sum = 0.f;
        #pragma unroll
        for (int d = 0; d < 64; d++) { float e = __expf(ep[d * 132] - mx); sum += e; ep[d * 132] = e; }
        const float inv = QSCALE / sum;

        // staging after eps: qb[g][col][33] u32 (conflict-free both directions)
        uint32_t* qb = (uint32_t*)(dsmem + 128 * 132 * 4);
        #pragma unroll
        for (int part = 0; part < 2; part++) {          // 0 = hi, 1 = lo
            uint32_t* qrow = qb + (g * 128 + col) * 33;
            #pragma unroll
            for (int p = 0; p < 32; p++) {
                float v0 = ep[(2 * p) * 132] * inv;
                float v1 = ep[(2 * p + 1) * 132] * inv;
                __nv_bfloat16 h0, l0, h1, l1;
                split_bf16(v0, h0, l0); split_bf16(v1, h1, l1);
                qrow[p] = (part == 0)
                    ? ((uint32_t)bfbits(h0) | ((uint32_t)bfbits(h1) << 16))
                    : ((uint32_t)bfbits(l0) | ((uint32_t)bfbits(l1) << 16));
            }
            __syncthreads();
            {   // coalesced writers: 8 warps = 2 groups x 4 col-chunks
                const int wg = wid >> 2, ch = wid & 3;
                uint32_t* dst = (part == 0) ? (uint32_t*)g_qhi : (uint32_t*)g_qlo;
                #pragma unroll
                for (int c = 0; c < 32; c++) {
                    const int colx = ch * 32 + c;
                    const long u = ((long)bz * NN + n0 + colx) * (HID / 2)
                                 + (m0 + wg * 64) / 2 + lane;
                    dst[u] = qb[(wg * 128 + colx) * 33 + lane];
                }
            }
            __syncthreads();
        }
    } else {
        float* Cp = C + (long)bz * sC + (long)m0 * ldC + n0;
        for (int i = tid; i < 128 * 32; i += 256) {
            const int r = i >> 5, c4 = (i & 31) << 2;
            float4 v = *(float4*)&eps[r * 132 + c4];
            if (BIAS) {
                const float bv = bias[m0 + r];
                v.x += bv; v.y += bv; v.z += bv; v.w += bv;
            }
            *(float4*)&Cp[(long)r * ldC + c4] = v;
        }
    }
}

// ---------------------------------------------------------------------------
// k: mask + softmax over n (4096). In-place fp32.
__global__ __launch_bounds__(256)
void softmax_k_kernel(const unsigned char* __restrict__ mask8)
{
    const int row = blockIdx.x;
    const int b = row >> 9;
    float* p = g_qkv + ((long)b * O3 + HID + (row & 511)) * NN;

    __shared__ float sv[NN];
    __shared__ float red[256];
    const int tid = threadIdx.x;
    const bool wide = (g_maskwide != 0);
    const int* mask32 = (const int*)mask8;

    float m = -INFINITY;
    for (int i = tid; i < NN; i += 256) {
        const bool on = wide ? (mask32[b * NN + i] != 0) : (mask8[b * NN + i] != 0);
        const float x = on ? p[i] : -INFINITY;
        sv[i] = x;
        m = fmaxf(m, x);
    }
    red[tid] = m; __syncthreads();
    for (int s = 128; s > 0; s >>= 1) { if (tid < s) red[tid] = fmaxf(red[tid], red[tid + s]); __syncthreads(); }
    m = red[0]; __syncthreads();

    float sum = 0.f;
    for (int i = tid; i < NN; i += 256) { const float e = __expf(sv[i] - m); sv[i] = e; sum += e; }
    red[tid] = sum; __syncthreads();
    for (int s = 128; s > 0; s >>= 1) { if (tid < s) red[tid] += red[tid + s]; __syncthreads(); }
    const float inv = 1.f / red[0];
    for (int i = tid; i < NN; i += 256) p[i] = sv[i] * inv;
}

// ---------------------------------------------------------------------------
__global__ __launch_bounds__(256)
void ctx_part_kernel()
{
    const int bh = blockIdx.x, ck = blockIdx.y;
    const int b = bh >> 3, h = bh & 7;
    const float* Kp = g_qkv + ((long)b * O3 + HID     + h * DH) * NN;
    const float* Vp = g_qkv + ((long)b * O3 + 2 * HID + h * DH) * NN;
    const int nbeg = ck * (NN / NCHUNK), nend = nbeg + (NN / NCHUNK);

    __shared__ float Ks[32][64];
    __shared__ float Vs[32][64];
    const int tid = threadIdx.x;
    const int lr = tid >> 2, lc = (tid & 3) << 3;
    const int tx = tid & 15, ty = tid >> 4;

    float acc[4][4];
    #pragma unroll
    for (int i = 0; i < 4; i++)
        #pragma unroll
        for (int j = 0; j < 4; j++) acc[i][j] = 0.f;

    for (int n0 = nbeg; n0 < nend; n0 += 32) {
        float4 ka = *(const float4*)(Kp + (long)lr * NN + n0 + lc);
        float4 kb = *(const float4*)(Kp + (long)lr * NN + n0 + lc + 4);
        float4 va = *(const float4*)(Vp + (long)lr * NN + n0 + lc);
        float4 vb = *(const float4*)(Vp + (long)lr * NN + n0 + lc + 4);
        Ks[lc + 0][lr] = ka.x; Ks[lc + 1][lr] = ka.y; Ks[lc + 2][lr] = ka.z; Ks[lc + 3][lr] = ka.w;
        Ks[lc + 4][lr] = kb.x; Ks[lc + 5][lr] = kb.y; Ks[lc + 6][lr] = kb.z; Ks[lc + 7][lr] = kb.w;
        Vs[lc + 0][lr] = va.x; Vs[lc + 1][lr] = va.y; Vs[lc + 2][lr] = va.z; Vs[lc + 3][lr] = va.w;
        Vs[lc + 4][lr] = vb.x; Vs[lc + 5][lr] = vb.y; Vs[lc + 6][lr] = vb.z; Vs[lc + 7][lr] = vb.w;
        __syncthreads();
        #pragma unroll
        for (int c = 0; c < 32; c++) {
            float4 k4 = *(const float4*)&Ks[c][ty * 4];
            float4 v4 = *(const float4*)&Vs[c][tx * 4];
            const float kr[4] = { k4.x, k4.y, k4.z, k4.w };
            const float vr[4] = { v4.x, v4.y, v4.z, v4.w };
            #pragma unroll
            for (int i = 0; i < 4; i++)
                #pragma unroll
                for (int j = 0; j < 4; j++)
                    acc[i][j] = fmaf(kr[i], vr[j], acc[i][j]);
        }
        __syncthreads();
    }
    float* Cp = g_ctxp[ck][bh];
    #pragma unroll
    for (int i = 0; i < 4; i++)
        #pragma unroll
        for (int j = 0; j < 4; j++)
            Cp[(ty * 4 + i) * DH + tx * 4 + j] = acc[i][j];
}

__global__ __launch_bounds__(256)
void ctx_reduce_kernel()
{
    const int idx = blockIdx.x * 256 + threadIdx.x;
    const int bh = idx >> 12, e = idx & 4095;
    float s = 0.f;
    #pragma unroll
    for (int c = 0; c < NCHUNK; c++) s += g_ctxp[c][bh][e];
    g_ctx[(long)bh * (DH * DH) + e] = s;
}

// ---------------------------------------------------------------------------
// Weff tiled mini-GEMM -> bf16 hi/lo.
__global__ __launch_bounds__(256)
void weff_kernel(const float* __restrict__ w_out)
{
    const int bh = blockIdx.x, oc = blockIdx.y;
    const int b = bh >> 3, h = bh & 7;
    const int o0 = oc * 64;

    __shared__ float ws[64][68];
    __shared__ float cs[64][68];
    const int tid = threadIdx.x;

    for (int i = tid; i < 64 * 64; i += 256) {
        const int r = i >> 6, e = i & 63;
        ws[e][r] = w_out[(long)(o0 + r) * HID + h * DH + e];
        cs[e][r] = g_ctx[((long)bh * DH + r) * DH + e];
    }
    __syncthreads();

    const int txx = tid & 15, tyy = tid >> 4;
    float acc[4][4];
    #pragma unroll
    for (int i = 0; i < 4; i++)
        #pragma unroll
        for (int j = 0; j < 4; j++) acc[i][j] = 0.f;

    #pragma unroll 4
    for (int e = 0; e < 64; e++) {
        float4 w4 = *(const float4*)&ws[e][tyy * 4];
        float4 c4 = *(const float4*)&cs[e][txx * 4];
        const float wr[4] = { w4.x, w4.y, w4.z, w4.w };
        const float cr[4] = { c4.x, c4.y, c4.z, c4.w };
        #pragma unroll
        for (int i = 0; i < 4; i++)
            #pragma unroll
            for (int j = 0; j < 4; j++)
                acc[i][j] = fmaf(wr[i], cr[j], acc[i][j]);
    }

    #pragma unroll
    for (int i = 0; i < 4; i++) {
        const long base = ((long)b * CC + o0 + tyy * 4 + i) * HID + h * DH + txx * 4;
        __nv_bfloat16 h0, l0, h1, l1, h2, l2, h3, l3;
        split_bf16(acc[i][0], h0, l0); split_bf16(acc[i][1], h1, l1);
        split_bf16(acc[i][2], h2, l2); split_bf16(acc[i][3], h3, l3);
        *(uint2*)&g_wfhi[base] = make_uint2(
            (uint32_t)bfbits(h0) | ((uint32_t)bfbits(h1) << 16),
            (uint32_t)bfbits(h2) | ((uint32_t)bfbits(h3) << 16));
        *(uint2*)&g_wflo[base] = make_uint2(
            (uint32_t)bfbits(l0) | ((uint32_t)bfbits(l1) << 16),
            (uint32_t)bfbits(l2) | ((uint32_t)bfbits(l3) << 16));
    }
}

// ---------------------------------------------------------------------------
typedef CUresult (*EncFn)(CUtensorMap*, CUtensorMapDataType, cuuint32_t, void*,
                          const cuuint64_t*, const cuuint64_t*, const cuuint32_t*,
                          const cuuint32_t*, CUtensorMapInterleave, CUtensorMapSwizzle,
                          CUtensorMapL2promotion, CUtensorMapFloatOOBfill);

static void make_desc(EncFn enc, CUtensorMap* m, void* base,
                      uint64_t d0, uint64_t d1, uint64_t d2)
{
    cuuint64_t dims[3] = { d0, d1, d2 };
    cuuint64_t strides[2] = { d0 * 2, d0 * d1 * 2 };
    cuuint32_t box[3] = { 64, 128, 1 };
    cuuint32_t es[3] = { 1, 1, 1 };
    enc(m, CU_TENSOR_MAP_DATA_TYPE_BFLOAT16, 3, base, dims, strides, box, es,
        CU_TENSOR_MAP_INTERLEAVE_NONE, CU_TENSOR_MAP_SWIZZLE_128B,
        CU_TENSOR_MAP_L2_PROMOTION_L2_128B, CU_TENSOR_MAP_FLOAT_OOB_FILL_NONE);
}

extern "C" void kernel_launch(void* const* d_in, const int* in_sizes, int n_in,
                              void* d_out, int out_size)
{
    const float* x      = (const float*)d_in[0];
    const unsigned char* mask = (const unsigned char*)d_in[1];
    const float* w_qkv  = (const float*)d_in[2];
    const float* w_out  = (const float*)d_in[3];
    const float* b_out  = (const float*)d_in[4];
    float* out = (float*)d_out;

    float *qkv_p;
    __nv_bfloat16 *whi_p, *wlo_p, *xhi_p, *xlo_p, *qhi_p, *qlo_p, *wfhi_p, *wflo_p;
    cudaGetSymbolAddress((void**)&qkv_p,  g_qkv);
    cudaGetSymbolAddress((void**)&whi_p,  g_whi);
    cudaGetSymbolAddress((void**)&wlo_p,  g_wlo);
    cudaGetSymbolAddress((void**)&xhi_p,  g_xhi);
    cudaGetSymbolAddress((void**)&xlo_p,  g_xlo);
    cudaGetSymbolAddress((void**)&qhi_p,  g_qhi);
    cudaGetSymbolAddress((void**)&qlo_p,  g_qlo);
    cudaGetSymbolAddress((void**)&wfhi_p, g_wfhi);
    cudaGetSymbolAddress((void**)&wflo_p, g_wflo);

    void* encf = nullptr;
    cudaDriverEntryPointQueryResult qr;
    cudaGetDriverEntryPoint("cuTensorMapEncodeTiled", &encf, cudaEnableDefault, &qr);
    EncFn enc = (EncFn)encf;

    CUtensorMap tWh, tWl, tXh, tXl, tQh, tQl, tFh, tFl;
    make_desc(enc, &tWh, whi_p,  512, 1536, 1);
    make_desc(enc, &tWl, wlo_p,  512, 1536, 1);
    make_desc(enc, &tXh, xhi_p,  512, 4096, 8);
    make_desc(enc, &tXl, xlo_p,  512, 4096, 8);
    make_desc(enc, &tQh, qhi_p,  512, 4096, 8);
    make_desc(enc, &tQl, qlo_p,  512, 4096, 8);
    make_desc(enc, &tFh, wfhi_p, 512, 512,  8);
    make_desc(enc, &tFl, wflo_p, 512, 512,  8);

    const int DSMEM = NSTAGE * STAGEB + 1024;   // 197632 B
    cudaFuncSetAttribute((const void*)tma_gemm_kernel<false, true>,
                         cudaFuncAttributeMaxDynamicSharedMemorySize, DSMEM);
    cudaFuncSetAttribute((const void*)tma_gemm_kernel<true, false>,
                         cudaFuncAttributeMaxDynamicSharedMemorySize, DSMEM);

    // 0) prep
    sniff_mask_kernel<<<1, 1>>>(mask);
    convert_w_kernel<<<(O3 * CC + 255) / 256, 256>>>(w_qkv);
    {
        dim3 g(NN / 32, CC / 64, NB);
        transpose_convert_x<<<g, dim3(32, 8)>>>(x);
    }
    // 1) qkv = w_qkv @ x  (TMA SW128 + mma.sync bf16x3; q tiles fused softmax)
    {
        dim3 g(NN / 128, O3 / 128, NB);
        tma_gemm_kernel<false, true><<<g, 256, DSMEM>>>(
            tWh, tWl, tXh, tXl, qkv_p, nullptr, (long)O3 * NN, NN, 0);
    }
    // 2) k mask + softmax (in place, fp32)
    softmax_k_kernel<<<NB * HID, 256>>>(mask);
    // 3) context: split-K partials + deterministic reduce
    {
        dim3 g(NB * NH, NCHUNK);
        ctx_part_kernel<<<g, 256>>>();
        ctx_reduce_kernel<<<(NB * NH * DH * DH) / 256, 256>>>();
    }
    // 4) Weff (folded w_out x ctx) -> bf16 hi/lo
    {
        dim3 g(NB * NH, CC / 64);
        weff_kernel<<<g, 256>>>(w_out);
    }
    // 5) out = Weff[b] @ qT[b]^T + b_out
    {
        dim3 g(NN / 128, CC / 128, NB);
        tma_gemm_kernel<true, false><<<g, 256, DSMEM>>>(
            tFh, tFl, tQh, tQl, out, b_out, (long)CC * NN, NN, 1);
    }
}

// round 16
// speedup vs baseline: 1.0608x; 1.0218x over previous
#include <cuda_runtime.h>
#include <cuda.h>
#include <cuda_bf16.h>
#include <math.h>
#include <stdint.h>
#include <string.h>

#define NB   8
#define NH   8
#define DH   64
#define CC   512
#define NN   4096
#define HID  512
#define O3   1536
#define QSCALE 0.125f   // 64^-0.5
#define KTOT 512
#define BK   64                  // bf16 K per stage (128B rows, SW128)
#define KSTEPS (KTOT / BK)       // 8
#define ATILEB (256 * 128)       // 32768 B  A operand tile (256 rows)
#define BTILEB (128 * 128)       // 16384 B  B operand tile (128 rows)
#define STAGEB (2 * ATILEB + 2 * BTILEB)   // 98304 B per stage
#define NSTAGE 2
#define NCHUNK 8                 // ctx split-K chunks over n

// ---------------- scratch (static device arrays; sanctioned) ----------------
__device__ float g_qkv[(size_t)NB * O3 * NN];          // fp32 q|k|v (q third unused)
__device__ float g_ctx[NB * NH * DH * DH];
__device__ float g_ctxp[NCHUNK][NB * NH][DH * DH];
__device__ int   g_maskwide;
__device__ float g_maskf[NB * NN];                     // mask as 0/1 float
__device__ float g_km[NB * HID], g_kinv[NB * HID];     // k-softmax row stats
__device__ __align__(256) __nv_bfloat16 g_whi[O3 * CC],  g_wlo[O3 * CC];
__device__ __align__(256) __nv_bfloat16 g_xhi[(size_t)NB * NN * CC], g_xlo[(size_t)NB * NN * CC];
__device__ __align__(256) __nv_bfloat16 g_qhi[(size_t)NB * NN * HID], g_qlo[(size_t)NB * NN * HID];
__device__ __align__(256) __nv_bfloat16 g_wfhi[NB * CC * HID], g_wflo[NB * CC * HID];

// ---------------- device helpers ----------------
__device__ __forceinline__ uint32_t smem_u32(const void* p) {
    uint32_t a;
    asm("{ .reg .u64 t; cvta.to.shared.u64 t, %1; cvt.u32.u64 %0, t; }" : "=r"(a) : "l"(p));
    return a;
}
__device__ __forceinline__ void ldsm4(uint32_t* r, uint32_t addr) {
    asm volatile("ldmatrix.sync.aligned.m8n8.x4.shared.b16 {%0,%1,%2,%3}, [%4];"
                 : "=r"(r[0]), "=r"(r[1]), "=r"(r[2]), "=r"(r[3]) : "r"(addr));
}
__device__ __forceinline__ void mma_bf16(float* d, const uint32_t* a, uint32_t b0, uint32_t b1) {
    asm volatile("mma.sync.aligned.m16n8k16.row.col.f32.bf16.bf16.f32 "
                 "{%0,%1,%2,%3}, {%4,%5,%6,%7}, {%8,%9}, {%0,%1,%2,%3};"
                 : "+f"(d[0]), "+f"(d[1]), "+f"(d[2]), "+f"(d[3])
                 : "r"(a[0]), "r"(a[1]), "r"(a[2]), "r"(a[3]), "r"(b0), "r"(b1));
}
__device__ __forceinline__ void mbar_init(uint32_t a, uint32_t c) {
    asm volatile("mbarrier.init.shared.b64 [%0], %1;" :: "r"(a), "r"(c) : "memory");
}
__device__ __forceinline__ void mbar_expect(uint32_t a, uint32_t bytes) {
    asm volatile("mbarrier.arrive.expect_tx.shared.b64 _, [%0], %1;" :: "r"(a), "r"(bytes) : "memory");
}
__device__ __forceinline__ void mbar_wait(uint32_t mbar, uint32_t parity) {
    uint32_t done;
    asm volatile("{ .reg .pred p; mbarrier.try_wait.parity.acquire.cta.shared::cta.b64 p, [%1], %2; selp.b32 %0,1,0,p; }"
                 : "=r"(done) : "r"(mbar), "r"(parity) : "memory");
    if (!done) {
        asm volatile("{ .reg .pred P1; WL%=: mbarrier.try_wait.parity.acquire.cta.shared::cta.b64 P1, [%0], %1, 0x989680; @P1 bra.uni WD%=; bra.uni WL%=; WD%=: }"
                     :: "r"(mbar), "r"(parity) : "memory");
    }
}
__device__ __forceinline__ void tma3d(uint32_t dst, const CUtensorMap* m,
                                      int cx, int cy, int cz, uint32_t bar) {
    asm volatile("cp.async.bulk.tensor.3d.shared::cta.global.tile.mbarrier::complete_tx::bytes "
                 "[%0], [%1, {%2, %3, %4}], [%5];"
                 :: "r"(dst), "l"(m), "r"(cx), "r"(cy), "r"(cz), "r"(bar) : "memory");
}
__device__ __forceinline__ void split_bf16(float v, __nv_bfloat16& hi, __nv_bfloat16& lo) {
    hi = __float2bfloat16(v);
    lo = __float2bfloat16(v - __bfloat162float(hi));
}
__device__ __forceinline__ unsigned short bfbits(__nv_bfloat16 x) {
    unsigned short u; memcpy(&u, &x, 2); return u;
}

// ---------------------------------------------------------------------------
__global__ void sniff_mask_kernel(const unsigned char* __restrict__ mask8) {
    g_maskwide = (mask8[1] == 0) ? 1 : 0;
}

// mask -> 0/1 float (removes dtype branch from hot paths)
__global__ __launch_bounds__(256) void mask_convert_kernel(const unsigned char* __restrict__ mask8) {
    const int i = blockIdx.x * 256 + threadIdx.x;     // < NB*NN
    const bool wide = (g_maskwide != 0);
    const bool on = wide ? (((const int*)mask8)[i] != 0) : (mask8[i] != 0);
    g_maskf[i] = on ? 1.f : 0.f;
}

__global__ __launch_bounds__(256) void convert_w_kernel(const float* __restrict__ w) {
    int i = blockIdx.x * 256 + threadIdx.x;
    if (i < O3 * CC) { __nv_bfloat16 h, l; split_bf16(w[i], h, l); g_whi[i] = h; g_wlo[i] = l; }
}

// x [b][c][n] fp32 -> xT hi/lo [b][n][c] bf16.
__global__ __launch_bounds__(256) void transpose_convert_x(const float* __restrict__ x) {
    __shared__ float t[64][33];
    const int b = blockIdx.z, n0 = blockIdx.x * 32, c0 = blockIdx.y * 64;
    const int tx = threadIdx.x, ty = threadIdx.y;              // 32 x 8
    #pragma unroll
    for (int cl = ty; cl < 64; cl += 8)
        t[cl][tx] = x[((long)b * CC + c0 + cl) * NN + n0 + tx];
    __syncthreads();
    const int lane = tx;
    #pragma unroll
    for (int rr = 0; rr < 4; rr++) {
        const int r = ty * 4 + rr;
        float v0 = t[2 * lane][r], v1 = t[2 * lane + 1][r];
        __nv_bfloat16 h0, l0, h1, l1;
        split_bf16(v0, h0, l0); split_bf16(v1, h1, l1);
        const long base = ((long)b * NN + n0 + r) * CC + c0 + 2 * lane;
        *(uint32_t*)&g_xhi[base] = (uint32_t)bfbits(h0) | ((uint32_t)bfbits(h1) << 16);
        *(uint32_t*)&g_xlo[base] = (uint32_t)bfbits(l0) | ((uint32_t)bfbits(l1) << 16);
    }
}

// ---------------------------------------------------------------------------
// bf16x3 GEMM: TMA (SW128) + mma.sync. 256x128 CTA tile, 512 thr, warps 4x4,
// warp tile 64x32, BK=64, 2-stage pipeline. QFUSE: q m-tiles get fused
// column-softmax + bf16 hi/lo split, written COALESCED via smem staging.
// (R11-proven configuration: measured 484us / 844.8us total.)
// ---------------------------------------------------------------------------
template<bool BIAS, bool QFUSE>
__global__ __launch_bounds__(512, 1)
void tma_gemm_kernel(const __grid_constant__ CUtensorMap tAh,
                     const __grid_constant__ CUtensorMap tAl,
                     const __grid_constant__ CUtensorMap tBh,
                     const __grid_constant__ CUtensorMap tBl,
                     float* __restrict__ C, const float* __restrict__ bias,
                     long sC, int ldC, int aBatch)
{
    extern __shared__ char dsmem[];
    __shared__ __align__(8) unsigned long long s_bar[NSTAGE];

    const int tid = threadIdx.x, lane = tid & 31, wid = tid >> 5;
    const int wm = wid >> 2, wn = wid & 3;            // warps 4x4
    const int m0 = blockIdx.y * 256, n0 = blockIdx.x * 128, bz = blockIdx.z;
    const int za = aBatch ? bz : 0;

    const uint32_t sb = (smem_u32(dsmem) + 1023u) & ~1023u;
    const uint32_t bar0 = smem_u32(&s_bar[0]);

    if (tid == 0) {
        #pragma unroll
        for (int i = 0; i < NSTAGE; i++) mbar_init(bar0 + i * 8, 1);
    }
    asm volatile("fence.proxy.async.shared::cta;" ::: "memory");
    __syncthreads();

    auto issue = [&](int s) {
        const int sl = s % NSTAGE;
        const uint32_t bar = bar0 + sl * 8;
        const uint32_t dst = sb + sl * STAGEB;
        const int k0 = s * BK;
        mbar_expect(bar, STAGEB);
        tma3d(dst,                           &tAh, k0, m0, za, bar);
        tma3d(dst + ATILEB,                  &tAl, k0, m0, za, bar);
        tma3d(dst + 2 * ATILEB,              &tBh, k0, n0, bz, bar);
        tma3d(dst + 2 * ATILEB + BTILEB,     &tBl, k0, n0, bz, bar);
    };
    if (tid == 0) { issue(0); issue(1); }

    // ldmatrix swizzled addressing (SW128, 128B rows)
    const int lr = lane & 15;
    const uint32_t xorv = (uint32_t)((lane & 7) << 4);
    const uint32_t acol = (uint32_t)((lane >> 4) * 16);
    const uint32_t aRow = (uint32_t)((wm * 64 + lr) * 128);
    const uint32_t bRow = (uint32_t)((wn * 32 + lr) * 128);

    float acc[4][4][4];
    #pragma unroll
    for (int i = 0; i < 4; i++)
        #pragma unroll
        for (int j = 0; j < 4; j++)
            #pragma unroll
            for (int r = 0; r < 4; r++) acc[i][j][r] = 0.f;

    for (int s = 0; s < KSTEPS; s++) {
        mbar_wait(bar0 + (s % NSTAGE) * 8, (uint32_t)((s / NSTAGE) & 1));
        const uint32_t stg = sb + (s % NSTAGE) * STAGEB;

        #pragma unroll
        for (int k16 = 0; k16 < 4; k16++) {
            const uint32_t kb = (uint32_t)(k16 * 32);
            const uint32_t csw = (acol + kb) ^ xorv;
            uint32_t ah[4][4], al[4][4], bhf[2][4], blf[2][4];
            #pragma unroll
            for (int mf = 0; mf < 4; mf++) {
                const uint32_t ro = aRow + (uint32_t)(mf * 16 * 128) + csw;
                ldsm4(ah[mf], stg + ro);
                ldsm4(al[mf], stg + ATILEB + ro);
            }
            #pragma unroll
            for (int nf = 0; nf < 2; nf++) {
                const uint32_t ro = bRow + (uint32_t)(nf * 16 * 128) + csw;
                ldsm4(bhf[nf], stg + 2 * ATILEB + ro);
                ldsm4(blf[nf], stg + 2 * ATILEB + BTILEB + ro);
            }
            #pragma unroll
            for (int t = 0; t < 3; t++) {
                #pragma unroll
                for (int mf = 0; mf < 4; mf++) {
                    #pragma unroll
                    for (int j = 0; j < 4; j++) {
                        const int nf = j >> 1, sel = j & 1;
                        if (t == 0)
                            mma_bf16(acc[mf][j], ah[mf], bhf[nf][sel], bhf[nf][sel + 2]);
                        else if (t == 1)
                            mma_bf16(acc[mf][j], ah[mf], blf[nf][sel], blf[nf][sel + 2]);
                        else
                            mma_bf16(acc[mf][j], al[mf], bhf[nf][sel], bhf[nf][sel + 2]);
                    }
                }
            }
        }

        __syncthreads();
        if (s + NSTAGE < KSTEPS && tid == 0) issue(s + NSTAGE);
    }

    // epilogue: fragments -> smem eps[256][132] fp32
    __syncthreads();
    float* eps = (float*)dsmem;
    const int fr = lane >> 2, fc = (lane & 3) * 2;
    #pragma unroll
    for (int mf = 0; mf < 4; mf++) {
        #pragma unroll
        for (int j = 0; j < 4; j++) {
            const int row = wm * 64 + mf * 16 + fr;
            const int col = wn * 32 + j * 8 + fc;
            eps[row * 132 + col]           = acc[mf][j][0];
            eps[row * 132 + col + 1]       = acc[mf][j][1];
            eps[(row + 8) * 132 + col]     = acc[mf][j][2];
            eps[(row + 8) * 132 + col + 1] = acc[mf][j][3];
        }
    }
    __syncthreads();

    if (QFUSE && m0 < 512) {
        // fused q softmax: thread -> (column n = tid&127, 64-row head group g = tid>>7)
        const int col = tid & 127, g = tid >> 7;
        float* ep = eps + (g * 64) * 132 + col;
        float mx = -INFINITY;
        #pragma unroll
        for (int d = 0; d < 64; d++) mx = fmaxf(mx, ep[d * 132]);
        float sum = 0.f;
        #pragma unroll
        for (int d = 0; d < 64; d++) { float e = __expf(ep[d * 132] - mx); sum += e; ep[d * 132] = e; }
        const float inv = QSCALE / sum;

        // staging buffer after eps: qb[g1][col][33] u32 (conflict-free both ways)
        uint32_t* qb = (uint32_t*)(dsmem + 256 * 132 * 4);
        const int g1 = g & 1;
        uint32_t* dsthi = (uint32_t*)g_qhi;
        uint32_t* dstlo = (uint32_t*)g_qlo;

        #pragma unroll
        for (int part = 0; part < 2; part++) {          // 0 = hi, 1 = lo
            #pragma unroll
            for (int gh = 0; gh < 2; gh++) {            // head-group half
                if ((g >> 1) == gh) {
                    uint32_t* qrow = qb + (g1 * 128 + col) * 33;
                    #pragma unroll
                    for (int p = 0; p < 32; p++) {
                        float v0 = ep[(2 * p) * 132] * inv;
                        float v1 = ep[(2 * p + 1) * 132] * inv;
                        __nv_bfloat16 h0, l0, h1, l1;
                        split_bf16(v0, h0, l0); split_bf16(v1, h1, l1);
                        qrow[p] = (part == 0)
                            ? ((uint32_t)bfbits(h0) | ((uint32_t)bfbits(h1) << 16))
                            : ((uint32_t)bfbits(l0) | ((uint32_t)bfbits(l1) << 16));
                    }
                }
                __syncthreads();
                if (wid < 8) {                           // coalesced writers
                    const int wg1 = wid >> 2, ch = wid & 3;
                    const int gg = gh * 2 + wg1;
                    uint32_t* dst = (part == 0) ? dsthi : dstlo;
                    #pragma unroll
                    for (int c = 0; c < 32; c++) {
                        const int colx = ch * 32 + c;
                        const long u = ((long)bz * NN + n0 + colx) * (HID / 2)
                                     + (m0 + gg * 64) / 2 + lane;
                        dst[u] = qb[(wg1 * 128 + colx) * 33 + lane];
                    }
                }
                __syncthreads();
            }
        }
    } else {
        float* Cp = C + (long)bz * sC + (long)m0 * ldC + n0;
        for (int i = tid; i < 256 * 32; i += 512) {
            const int r = i >> 5, c4 = (i & 31) << 2;
            float4 v = *(float4*)&eps[r * 132 + c4];
            if (BIAS) {
                const float bv = bias[m0 + r];
                v.x += bv; v.y += bv; v.z += bv; v.w += bv;
            }
            *(float4*)&Cp[(long)r * ldC + c4] = v;
        }
    }
}

// ---------------------------------------------------------------------------
// k row stats: masked max + 1/sum(exp) per (b, hd) row. No writeback of Ksoft.
__global__ __launch_bounds__(256)
void rowstat_k_kernel()
{
    const int row = blockIdx.x;           // < NB*HID
    const int b = row >> 9;
    const float* p = g_qkv + ((long)b * O3 + HID + (row & 511)) * NN;
    const float* mf = g_maskf + (long)b * NN;

    __shared__ float sv[NN];
    __shared__ float red[256];
    const int tid = threadIdx.x;

    float m = -INFINITY;
    for (int i = tid; i < NN; i += 256) {
        const float x = (mf[i] != 0.f) ? p[i] : -INFINITY;
        sv[i] = x;
        m = fmaxf(m, x);
    }
    red[tid] = m; __syncthreads();
    for (int s = 128; s > 0; s >>= 1) { if (tid < s) red[tid] = fmaxf(red[tid], red[tid + s]); __syncthreads(); }
    m = red[0]; __syncthreads();

    float sum = 0.f;
    for (int i = tid; i < NN; i += 256) sum += __expf(sv[i] - m);
    red[tid] = sum; __syncthreads();
    for (int s = 128; s > 0; s >>= 1) { if (tid < s) red[tid] += red[tid + s]; __syncthreads(); }
    if (tid == 0) { g_km[row] = m; g_kinv[row] = 1.f / red[0]; }
}

// ---------------------------------------------------------------------------
// ctx partial with on-the-fly k softmax:
// p = (exp(k - m) * inv) * maskf  — numerically identical to the stored-Ksoft
// path (maskf in {0,1} exact).
__global__ __launch_bounds__(256)
void ctx_part_kernel()
{
    const int bh = blockIdx.x, ck = blockIdx.y;
    const int b = bh >> 3, h = bh & 7;
    const float* Kp = g_qkv + ((long)b * O3 + HID     + h * DH) * NN;
    const float* Vp = g_qkv + ((long)b * O3 + 2 * HID + h * DH) * NN;
    const float* Mp = g_maskf + (long)b * NN;
    const int nbeg = ck * (NN / NCHUNK), nend = nbeg + (NN / NCHUNK);

    __shared__ float Ks[32][64];
    __shared__ float Vs[32][64];
    const int tid = threadIdx.x;
    const int lr = tid >> 2, lc = (tid & 3) << 3;
    const int tx = tid & 15, ty = tid >> 4;

    const float km  = g_km[b * HID + h * DH + lr];
    const float kiv = g_kinv[b * HID + h * DH + lr];

    float acc[4][4];
    #pragma unroll
    for (int i = 0; i < 4; i++)
        #pragma unroll
        for (int j = 0; j < 4; j++) acc[i][j] = 0.f;

    for (int n0 = nbeg; n0 < nend; n0 += 32) {
        float4 ka = *(const float4*)(Kp + (long)lr * NN + n0 + lc);
        float4 kb = *(const float4*)(Kp + (long)lr * NN + n0 + lc + 4);
        float4 va = *(const float4*)(Vp + (long)lr * NN + n0 + lc);
        float4 vb = *(const float4*)(Vp + (long)lr * NN + n0 + lc + 4);
        float4 ma = *(const float4*)(Mp + n0 + lc);
        float4 mb = *(const float4*)(Mp + n0 + lc + 4);
        Ks[lc + 0][lr] = (__expf(ka.x - km) * kiv) * ma.x;
        Ks[lc + 1][lr] = (__expf(ka.y - km) * kiv) * ma.y;
        Ks[lc + 2][lr] = (__expf(ka.z - km) * kiv) * ma.z;
        Ks[lc + 3][lr] = (__expf(ka.w - km) * kiv) * ma.w;
        Ks[lc + 4][lr] = (__expf(kb.x - km) * kiv) * mb.x;
        Ks[lc + 5][lr] = (__expf(kb.y - km) * kiv) * mb.y;
        Ks[lc + 6][lr] = (__expf(kb.z - km) * kiv) * mb.z;
        Ks[lc + 7][lr] = (__expf(kb.w - km) * kiv) * mb.w;
        Vs[lc + 0][lr] = va.x; Vs[lc + 1][lr] = va.y; Vs[lc + 2][lr] = va.z; Vs[lc + 3][lr] = va.w;
        Vs[lc + 4][lr] = vb.x; Vs[lc + 5][lr] = vb.y; Vs[lc + 6][lr] = vb.z; Vs[lc + 7][lr] = vb.w;
        __syncthreads();
        #pragma unroll
        for (int c = 0; c < 32; c++) {
            float4 k4 = *(const float4*)&Ks[c][ty * 4];
            float4 v4 = *(const float4*)&Vs[c][tx * 4];
            const float kr[4] = { k4.x, k4.y, k4.z, k4.w };
            const float vr[4] = { v4.x, v4.y, v4.z, v4.w };
            #pragma unroll
            for (int i = 0; i < 4; i++)
                #pragma unroll
                for (int j = 0; j < 4; j++)
                    acc[i][j] = fmaf(kr[i], vr[j], acc[i][j]);
        }
        __syncthreads();
    }
    float* Cp = g_ctxp[ck][bh];
    #pragma unroll
    for (int i = 0; i < 4; i++)
        #pragma unroll
        for (int j = 0; j < 4; j++)
            Cp[(ty * 4 + i) * DH + tx * 4 + j] = acc[i][j];
}

__global__ __launch_bounds__(256)
void ctx_reduce_kernel()
{
    const int idx = blockIdx.x * 256 + threadIdx.x;
    const int bh = idx >> 12, e = idx & 4095;
    float s = 0.f;
    #pragma unroll
    for (int c = 0; c < NCHUNK; c++) s += g_ctxp[c][bh][e];
    g_ctx[(long)bh * (DH * DH) + e] = s;
}

// ---------------------------------------------------------------------------
// Weff tiled mini-GEMM -> bf16 hi/lo.
__global__ __launch_bounds__(256)
void weff_kernel(const float* __restrict__ w_out)
{
    const int bh = blockIdx.x, oc = blockIdx.y;
    const int b = bh >> 3, h = bh & 7;
    const int o0 = oc * 64;

    __shared__ float ws[64][68];
    __shared__ float cs[64][68];
    const int tid = threadIdx.x;

    for (int i = tid; i < 64 * 64; i += 256) {
        const int r = i >> 6, e = i & 63;
        ws[e][r] = w_out[(long)(o0 + r) * HID + h * DH + e];
        cs[e][r] = g_ctx[((long)bh * DH + r) * DH + e];
    }
    __syncthreads();

    const int txx = tid & 15, tyy = tid >> 4;
    float acc[4][4];
    #pragma unroll
    for (int i = 0; i < 4; i++)
        #pragma unroll
        for (int j = 0; j < 4; j++) acc[i][j] = 0.f;

    #pragma unroll 4
    for (int e = 0; e < 64; e++) {
        float4 w4 = *(const float4*)&ws[e][tyy * 4];
        float4 c4 = *(const float4*)&cs[e][txx * 4];
        const float wr[4] = { w4.x, w4.y, w4.z, w4.w };
        const float cr[4] = { c4.x, c4.y, c4.z, c4.w };
        #pragma unroll
        for (int i = 0; i < 4; i++)
            #pragma unroll
            for (int j = 0; j < 4; j++)
                acc[i][j] = fmaf(wr[i], cr[j], acc[i][j]);
    }

    #pragma unroll
    for (int i = 0; i < 4; i++) {
        const long base = ((long)b * CC + o0 + tyy * 4 + i) * HID + h * DH + txx * 4;
        __nv_bfloat16 h0, l0, h1, l1, h2, l2, h3, l3;
        split_bf16(acc[i][0], h0, l0); split_bf16(acc[i][1], h1, l1);
        split_bf16(acc[i][2], h2, l2); split_bf16(acc[i][3], h3, l3);
        *(uint2*)&g_wfhi[base] = make_uint2(
            (uint32_t)bfbits(h0) | ((uint32_t)bfbits(h1) << 16),
            (uint32_t)bfbits(h2) | ((uint32_t)bfbits(h3) << 16));
        *(uint2*)&g_wflo[base] = make_uint2(
            (uint32_t)bfbits(l0) | ((uint32_t)bfbits(l1) << 16),
            (uint32_t)bfbits(l2) | ((uint32_t)bfbits(l3) << 16));
    }
}

// ---------------------------------------------------------------------------
typedef CUresult (*EncFn)(CUtensorMap*, CUtensorMapDataType, cuuint32_t, void*,
                          const cuuint64_t*, const cuuint64_t*, const cuuint32_t*,
                          const cuuint32_t*, CUtensorMapInterleave, CUtensorMapSwizzle,
                          CUtensorMapL2promotion, CUtensorMapFloatOOBfill);

static void make_desc(EncFn enc, CUtensorMap* m, void* base,
                      uint64_t d0, uint64_t d1, uint64_t d2, uint32_t box1)
{
    cuuint64_t dims[3] = { d0, d1, d2 };
    cuuint64_t strides[2] = { d0 * 2, d0 * d1 * 2 };
    cuuint32_t box[3] = { 64, box1, 1 };
    cuuint32_t es[3] = { 1, 1, 1 };
    enc(m, CU_TENSOR_MAP_DATA_TYPE_BFLOAT16, 3, base, dims, strides, box, es,
        CU_TENSOR_MAP_INTERLEAVE_NONE, CU_TENSOR_MAP_SWIZZLE_128B,
        CU_TENSOR_MAP_L2_PROMOTION_L2_128B, CU_TENSOR_MAP_FLOAT_OOB_FILL_NONE);
}

extern "C" void kernel_launch(void* const* d_in, const int* in_sizes, int n_in,
                              void* d_out, int out_size)
{
    const float* x      = (const float*)d_in[0];
    const unsigned char* mask = (const unsigned char*)d_in[1];
    const float* w_qkv  = (const float*)d_in[2];
    const float* w_out  = (const float*)d_in[3];
    const float* b_out  = (const float*)d_in[4];
    float* out = (float*)d_out;

    float *qkv_p;
    __nv_bfloat16 *whi_p, *wlo_p, *xhi_p, *xlo_p, *qhi_p, *qlo_p, *wfhi_p, *wflo_p;
    cudaGetSymbolAddress((void**)&qkv_p,  g_qkv);
    cudaGetSymbolAddress((void**)&whi_p,  g_whi);
    cudaGetSymbolAddress((void**)&wlo_p,  g_wlo);
    cudaGetSymbolAddress((void**)&xhi_p,  g_xhi);
    cudaGetSymbolAddress((void**)&xlo_p,  g_xlo);
    cudaGetSymbolAddress((void**)&qhi_p,  g_qhi);
    cudaGetSymbolAddress((void**)&qlo_p,  g_qlo);
    cudaGetSymbolAddress((void**)&wfhi_p, g_wfhi);
    cudaGetSymbolAddress((void**)&wflo_p, g_wflo);

    void* encf = nullptr;
    cudaDriverEntryPointQueryResult qr;
    cudaGetDriverEntryPoint("cuTensorMapEncodeTiled", &encf, cudaEnableDefault, &qr);
    EncFn enc = (EncFn)encf;

    CUtensorMap tWh, tWl, tXh, tXl, tQh, tQl, tFh, tFl;
    make_desc(enc, &tWh, whi_p,  512, 1536, 1, 256);
    make_desc(enc, &tWl, wlo_p,  512, 1536, 1, 256);
    make_desc(enc, &tXh, xhi_p,  512, 4096, 8, 128);
    make_desc(enc, &tXl, xlo_p,  512, 4096, 8, 128);
    make_desc(enc, &tQh, qhi_p,  512, 4096, 8, 128);
    make_desc(enc, &tQl, qlo_p,  512, 4096, 8, 128);
    make_desc(enc, &tFh, wfhi_p, 512, 512,  8, 256);
    make_desc(enc, &tFl, wflo_p, 512, 512,  8, 256);

    const int DSMEM = NSTAGE * STAGEB + 1024;   // 197632 B
    cudaFuncSetAttribute((const void*)tma_gemm_kernel<false, true>,
                         cudaFuncAttributeMaxDynamicSharedMemorySize, DSMEM);
    cudaFuncSetAttribute((const void*)tma_gemm_kernel<true, false>,
                         cudaFuncAttributeMaxDynamicSharedMemorySize, DSMEM);

    // 0) prep
    sniff_mask_kernel<<<1, 1>>>(mask);
    mask_convert_kernel<<<(NB * NN) / 256, 256>>>(mask);
    convert_w_kernel<<<(O3 * CC + 255) / 256, 256>>>(w_qkv);
    {
        dim3 g(NN / 32, CC / 64, NB);
        transpose_convert_x<<<g, dim3(32, 8)>>>(x);
    }
    // 1) qkv = w_qkv @ x  (TMA + mma.sync bf16x3; q tiles get fused softmax)
    {
        dim3 g(NN / 128, O3 / 256, NB);
        tma_gemm_kernel<false, true><<<g, 512, DSMEM>>>(
            tWh, tWl, tXh, tXl, qkv_p, nullptr, (long)O3 * NN, NN, 0);
    }
    // 2) k softmax row stats (no Ksoft writeback)
    rowstat_k_kernel<<<NB * HID, 256>>>();
    // 3) context: on-the-fly softmax + split-K partials + deterministic reduce
    {
        dim3 g(NB * NH, NCHUNK);
        ctx_part_kernel<<<g, 256>>>();
        ctx_reduce_kernel<<<(NB * NH * DH * DH) / 256, 256>>>();
    }
    // 4) Weff (folded w_out x ctx) -> bf16 hi/lo
    {
        dim3 g(NB * NH, CC / 64);
        weff_kernel<<<g, 256>>>(w_out);
    }
    // 5) out = Weff[b] @ qT[b]^T + b_out
    {
        dim3 g(NN / 128, CC / 256, NB);
        tma_gemm_kernel<true, false><<<g, 512, DSMEM>>>(
            tFh, tFl, tQh, tQl, out, b_out, (long)CC * NN, NN, 1);
    }
}